// round 1
// baseline (speedup 1.0000x reference)
#include <cuda_runtime.h>
#include <stdint.h>

#define BATCH 8192
// layer sizes
// conv1: in [B,1,28,28] -> out [B,32,14,14] (196 pos), k=5 s=2 p=2
// conv2: in [B,32,14,14] -> out [B,64,8,8] (64 pos),   k=4 s=2 p=2
// fc:    [B,4096] x [10,4096]^T -> [B,10]

// ---------------- device globals (scratch; no cudaMalloc allowed) ------------
__device__ signed char        g_c1[(size_t)BATCH * 196 * 32];  // [n][pos196][c32] int8
__device__ short              g_c2[(size_t)BATCH * 4096];      // [n][pos64][co64] int16
__device__ short              g_fc[(size_t)BATCH * 10];
__device__ unsigned int       g_w1b[160];                      // [co32][row5], 5-bit rows
__device__ unsigned int       g_w2b[1024];                     // [co64][tap16], bit=ci
__device__ unsigned long long g_w3b[640];                      // [o10][p64],   bit=c
// stats: [0:32) sum1 [32:64) sq1 [64:128) sum2 [128:192) sq2 [192:202) sum3 [202:212) sq3
__device__ unsigned long long g_stats[212];
__device__ float g_m1[32], g_s1[32], g_bb1[32];
__device__ float g_m2[64], g_s2[64], g_bb2[64];

// ---------------- reset (device globals persist across graph replays) --------
__global__ void reset_kernel() {
    int t = threadIdx.x;
    if (t < 212) g_stats[t] = 0ull;
}

// ---------------- weight binarization + packing ------------------------------
__global__ void pack_weights(const float* __restrict__ w1,
                             const float* __restrict__ w2,
                             const float* __restrict__ w3) {
    int t = blockIdx.x * blockDim.x + threadIdx.x;
    if (t < 160) {                       // w1 [32,1,5,5]: co=t/5, row=t%5
        int co = t / 5, r = t % 5;
        unsigned v = 0;
        #pragma unroll
        for (int kx = 0; kx < 5; kx++)
            v |= (unsigned)(w1[(co * 5 + r) * 5 + kx] > 0.f) << kx;
        g_w1b[t] = v;
    } else if (t < 160 + 1024) {         // w2 [64,32,4,4]: bit ci
        int i = t - 160;
        int co = i >> 4, tap = i & 15;
        int ky = tap >> 2, kx = tap & 3;
        unsigned v = 0;
        #pragma unroll
        for (int ci = 0; ci < 32; ci++)
            v |= (unsigned)(w2[((co * 32 + ci) * 4 + ky) * 4 + kx] > 0.f) << ci;
        g_w2b[i] = v;
    } else if (t < 160 + 1024 + 640) {   // w3 [10,4096]: word[o][p] bit c = w3[o, c*64+p]
        int i = t - 1184;
        int o = i >> 6, p = i & 63;
        unsigned long long v = 0ull;
        #pragma unroll
        for (int c = 0; c < 64; c++)
            v |= (unsigned long long)(w3[o * 4096 + c * 64 + p] > 0.f) << c;
        g_w3b[i] = v;
    }
}

// ---------------- conv1: bitpacked rows, popcount, + exact channel stats -----
__global__ void __launch_bounds__(224) conv1_kernel(const float* __restrict__ x) {
    __shared__ unsigned xv[28], xm[28];       // value bit / nonzero bit per row
    __shared__ unsigned w1s[160];
    __shared__ int dots[196 * 33];            // padded (stride 33) to avoid bank conflicts
    __shared__ int part_s[7 * 32], part_q[7 * 32];

    int n = blockIdx.x;
    int t = threadIdx.x;

    if (t < 160) w1s[t] = g_w1b[t];
    if (t < 28) {
        const float* row = x + (size_t)n * 784 + t * 28;
        unsigned v = 0, m = 0;
        #pragma unroll
        for (int j = 0; j < 28; j++) {
            float f = row[j];
            v |= (unsigned)(f > 0.f)  << j;
            m |= (unsigned)(f != 0.f) << j;   // sign(0)=0 -> tap contributes 0
        }
        xv[t] = v; xm[t] = m;
    }
    __syncthreads();

    if (t < 196) {
        int y = t / 14, xo = t % 14;
        int iy0 = 2 * y - 2, ix0 = 2 * xo - 2;
        unsigned sv[5], sm[5];
        int basec = 0;
        #pragma unroll
        for (int r = 0; r < 5; r++) {
            int iy = iy0 + r;
            unsigned v = 0, m = 0;
            if (iy >= 0 && iy < 28) {
                unsigned xvw = xv[iy], xmw = xm[iy];
                if (ix0 >= 0) { v = xvw >> ix0;     m = xmw >> ix0; }
                else          { v = xvw << (-ix0);  m = xmw << (-ix0); }
                m &= 31u;
            }
            sv[r] = v; sm[r] = m;
            basec += __popc(m);
        }
        unsigned pack[8] = {0, 0, 0, 0, 0, 0, 0, 0};
        #pragma unroll
        for (int co = 0; co < 32; co++) {
            int mm = 0;
            #pragma unroll
            for (int r = 0; r < 5; r++)
                mm += __popc((sv[r] ^ w1s[co * 5 + r]) & sm[r]);
            int d = basec - 2 * mm;            // range [-25, 25]
            dots[t * 33 + co] = d;
            pack[co >> 2] |= ((unsigned)d & 0xFFu) << ((co & 3) * 8);
        }
        uint4* dst = (uint4*)(g_c1 + ((size_t)n * 196 + t) * 32);
        dst[0] = make_uint4(pack[0], pack[1], pack[2], pack[3]);
        dst[1] = make_uint4(pack[4], pack[5], pack[6], pack[7]);
    }
    __syncthreads();

    // per-channel block reduction (no shared atomics)
    {
        int c = t & 31, grp = t >> 5;   // 7 warps
        int s = 0, q = 0;
        for (int i = grp; i < 196; i += 7) {
            int v = dots[i * 33 + c];
            s += v; q += v * v;
        }
        part_s[grp * 32 + c] = s;
        part_q[grp * 32 + c] = q;
    }
    __syncthreads();
    if (t < 32) {
        int s = 0, q = 0;
        #pragma unroll
        for (int g = 0; g < 7; g++) { s += part_s[g * 32 + t]; q += part_q[g * 32 + t]; }
        atomicAdd(&g_stats[t],      (unsigned long long)(long long)s);
        atomicAdd(&g_stats[32 + t], (unsigned long long)(long long)q);
    }
}

// ---------------- BN parameter computation (exact integer sums) --------------
__global__ void bn_prep(const float* __restrict__ g, const float* __restrict__ b, int sel) {
    int t = threadIdx.x;
    int nch = (sel == 0) ? 32 : 64;
    if (t >= nch) return;
    int off_sum = (sel == 0) ? 0 : 64;
    int off_sq  = (sel == 0) ? 32 : 128;
    long long count = (sel == 0) ? (long long)BATCH * 196 : (long long)BATCH * 64;
    long long s = (long long)g_stats[off_sum + t];
    long long q = (long long)g_stats[off_sq + t];
    double m   = (double)s / (double)count;
    double var = (double)q / (double)count - m * m;     // biased variance
    float scale = (float)((double)g[t] / sqrt(var + 1e-5));
    if (sel == 0) { g_m1[t] = (float)m; g_s1[t] = scale; g_bb1[t] = b[t]; }
    else          { g_m2[t] = (float)m; g_s2[t] = scale; g_bb2[t] = b[t]; }
}

// ---------------- conv2: binarize h1 on the fly, 32-ch XNOR-popcount ---------
__global__ void __launch_bounds__(256) conv2_kernel() {
    __shared__ unsigned h1s[196];
    __shared__ unsigned w2s[1024];
    __shared__ float m1[32], s1[32], bb1[32];
    __shared__ int sout[64 * 65];             // [pos][co] padded stride 65
    __shared__ int part_s[4 * 64], part_q[4 * 64];

    int n = blockIdx.x, t = threadIdx.x;

    for (int i = t; i < 1024; i += 256) w2s[i] = g_w2b[i];
    if (t < 32) { m1[t] = g_m1[t]; s1[t] = g_s1[t]; bb1[t] = g_bb1[t]; }
    __syncthreads();

    if (t < 196) {
        const uint4* src = (const uint4*)(g_c1 + ((size_t)n * 196 + t) * 32);
        uint4 a = src[0], bb = src[1];
        unsigned words[8] = {a.x, a.y, a.z, a.w, bb.x, bb.y, bb.z, bb.w};
        unsigned w = 0;
        #pragma unroll
        for (int k = 0; k < 8; k++) {
            unsigned wd = words[k];
            #pragma unroll
            for (int j = 0; j < 4; j++) {
                int c = k * 4 + j;
                int v = (int)(signed char)(wd >> (j * 8));
                float bv = ((float)v - m1[c]) * s1[c] + bb1[c];
                w |= (unsigned)(bv > 0.f) << c;
            }
        }
        h1s[t] = w;
    }
    __syncthreads();

    int pos = t & 63, cog = t >> 6;
    int y = pos >> 3, xo = pos & 7;
    unsigned inw[16];
    unsigned vm = 0;
    #pragma unroll
    for (int ky = 0; ky < 4; ky++)
        #pragma unroll
        for (int kx = 0; kx < 4; kx++) {
            int iy = 2 * y - 2 + ky, ix = 2 * xo - 2 + kx;
            int tap = ky * 4 + kx;
            bool valid = (iy >= 0) & (iy < 14) & (ix >= 0) & (ix < 14);
            inw[tap] = valid ? h1s[iy * 14 + ix] : 0u;
            vm |= (unsigned)valid << tap;
        }
    int nval = __popc(vm);
    int cobase = cog * 16;
    #pragma unroll
    for (int j = 0; j < 16; j++) {
        int co = cobase + j;
        int mm = 0;
        #pragma unroll
        for (int tap = 0; tap < 16; tap++) {
            unsigned wv = w2s[co * 16 + tap];
            if (vm & (1u << tap)) mm += __popc(inw[tap] ^ wv);
        }
        sout[pos * 65 + co] = 32 * nval - 2 * mm;   // range [-512, 512]
    }
    __syncthreads();

    // write out [n][pos][co] as int16, coalesced
    for (int idx = t; idx < 4096; idx += 256) {
        int p = idx >> 6, co = idx & 63;
        g_c2[(size_t)n * 4096 + idx] = (short)sout[p * 65 + co];
    }
    // per-channel stats
    {
        int co = t & 63, grp = t >> 6;   // 4 groups
        int s = 0, q = 0;
        for (int p = grp; p < 64; p += 4) {
            int v = sout[p * 65 + co];
            s += v; q += v * v;
        }
        part_s[grp * 64 + co] = s;
        part_q[grp * 64 + co] = q;
    }
    __syncthreads();
    if (t < 64) {
        int s = 0, q = 0;
        #pragma unroll
        for (int g = 0; g < 4; g++) { s += part_s[g * 64 + t]; q += part_q[g * 64 + t]; }
        atomicAdd(&g_stats[64 + t],  (unsigned long long)(long long)s);
        atomicAdd(&g_stats[128 + t], (unsigned long long)(long long)q);
    }
}

// ---------------- fc: binarize h2, 64-bit XNOR-popcount, + stats -------------
__global__ void __launch_bounds__(256) fc_kernel() {
    __shared__ unsigned long long w3s[640];
    __shared__ float m2[64], s2[64], bb2[64];
    __shared__ int warp_part[8][10];

    int t = threadIdx.x;
    for (int i = t; i < 640; i += 256) w3s[i] = g_w3b[i];
    if (t < 64) { m2[t] = g_m2[t]; s2[t] = g_s2[t]; bb2[t] = g_bb2[t]; }
    __syncthreads();

    int sub = t >> 6, p = t & 63;
    int n = blockIdx.x * 4 + sub;

    // load 64 int16 (128B, aligned), binarize, pack bit c
    const uint4* src4 = (const uint4*)(g_c2 + (size_t)n * 4096 + p * 64);
    unsigned long long hw = 0ull;
    #pragma unroll
    for (int k = 0; k < 8; k++) {
        uint4 v4 = src4[k];
        unsigned arr[4] = {v4.x, v4.y, v4.z, v4.w};
        #pragma unroll
        for (int j = 0; j < 4; j++) {
            unsigned wd = arr[j];
            int c0 = k * 8 + j * 2;
            int vlo = (int)(short)(wd & 0xFFFF);
            int vhi = (int)(short)(wd >> 16);
            float blo = ((float)vlo - m2[c0])     * s2[c0]     + bb2[c0];
            float bhi = ((float)vhi - m2[c0 + 1]) * s2[c0 + 1] + bb2[c0 + 1];
            hw |= (unsigned long long)(blo > 0.f) << c0;
            hw |= (unsigned long long)(bhi > 0.f) << (c0 + 1);
        }
    }

    int contrib[10];
    #pragma unroll
    for (int o = 0; o < 10; o++)
        contrib[o] = 64 - 2 * __popcll(hw ^ w3s[o * 64 + p]);

    #pragma unroll
    for (int o = 0; o < 10; o++) {
        int v = __reduce_add_sync(0xFFFFFFFFu, contrib[o]);
        if ((t & 31) == 0) warp_part[t >> 5][o] = v;
    }
    __syncthreads();
    if (p < 10) {
        int v = warp_part[sub * 2][p] + warp_part[sub * 2 + 1][p];
        g_fc[(size_t)n * 10 + p] = (short)v;
        atomicAdd(&g_stats[192 + p], (unsigned long long)(long long)v);
        atomicAdd(&g_stats[202 + p], (unsigned long long)(long long)(v * v));
    }
}

// ---------------- final BN1d epilogue ----------------------------------------
__global__ void out_kernel(const float* __restrict__ g3, const float* __restrict__ b3,
                           float* __restrict__ out) {
    int i = blockIdx.x * blockDim.x + threadIdx.x;
    if (i >= BATCH * 10) return;
    int o = i % 10;
    long long s = (long long)g_stats[192 + o];
    long long q = (long long)g_stats[202 + o];
    double m   = (double)s / (double)BATCH;
    double var = (double)q / (double)BATCH - m * m;
    float v = (float)g_fc[i];
    out[i] = (float)(((double)v - m) / sqrt(var + 1e-5) * (double)g3[o] + (double)b3[o]);
}

// ---------------- launch ------------------------------------------------------
extern "C" void kernel_launch(void* const* d_in, const int* in_sizes, int n_in,
                              void* d_out, int out_size) {
    const float* x  = (const float*)d_in[0];
    const float* w1 = (const float*)d_in[1];
    const float* g1 = (const float*)d_in[2];
    const float* b1 = (const float*)d_in[3];
    const float* w2 = (const float*)d_in[4];
    const float* g2 = (const float*)d_in[5];
    const float* b2 = (const float*)d_in[6];
    const float* w3 = (const float*)d_in[7];
    const float* g3 = (const float*)d_in[8];
    const float* b3 = (const float*)d_in[9];
    float* out = (float*)d_out;

    reset_kernel<<<1, 256>>>();
    pack_weights<<<8, 256>>>(w1, w2, w3);
    conv1_kernel<<<BATCH, 224>>>(x);
    bn_prep<<<1, 64>>>(g1, b1, 0);
    conv2_kernel<<<BATCH, 256>>>();
    bn_prep<<<1, 64>>>(g2, b2, 1);
    fc_kernel<<<BATCH / 4, 256>>>();
    out_kernel<<<(BATCH * 10 + 255) / 256, 256>>>(g3, b3, out);
}

// round 2
// speedup vs baseline: 1.0070x; 1.0070x over previous
#include <cuda_runtime.h>
#include <stdint.h>

#define BATCH 8192
// conv1: in [B,1,28,28] -> out [B,32,14,14] (196 pos), k=5 s=2 p=2
// conv2: in [B,32,14,14] -> out [B,64,8,8]  (64 pos),  k=4 s=2 p=2
// fc:    [B,4096] x [10,4096]^T -> [B,10]

// ---------------- device globals (scratch; no cudaMalloc allowed) ------------
__device__ signed char        g_c1[(size_t)BATCH * 196 * 32];  // [n][pos196][c32] int8
__device__ short              g_c2[(size_t)BATCH * 4096];      // [n][pos64][co64] int16
__device__ short              g_fc[(size_t)BATCH * 10];
__device__ unsigned int       g_w1b[160];                      // [co32][row5], 5-bit rows
__device__ unsigned int       g_w2b[1024];                     // [co64][tap16], bit=ci
__device__ unsigned long long g_w3b[640];                      // [o10][p64],   bit=c
// stats: [0:32) sum1 [32:64) sq1 [64:128) sum2 [128:192) sq2 [192:202) sum3 [202:212) sq3
__device__ unsigned long long g_stats[212];

// ---------------- init: reset stats + binarize/pack weights ------------------
__global__ void init_kernel(const float* __restrict__ w1,
                            const float* __restrict__ w2,
                            const float* __restrict__ w3) {
    int t = blockIdx.x * blockDim.x + threadIdx.x;
    if (blockIdx.x == 0 && threadIdx.x < 212) g_stats[threadIdx.x] = 0ull;
    if (t < 160) {                       // w1 [32,1,5,5]: co=t/5, row=t%5
        int co = t / 5, r = t % 5;
        unsigned v = 0;
        #pragma unroll
        for (int kx = 0; kx < 5; kx++)
            v |= (unsigned)(w1[(co * 5 + r) * 5 + kx] > 0.f) << kx;
        g_w1b[t] = v;
    } else if (t < 160 + 1024) {         // w2 [64,32,4,4]: bit ci
        int i = t - 160;
        int co = i >> 4, tap = i & 15;
        int ky = tap >> 2, kx = tap & 3;
        unsigned v = 0;
        #pragma unroll
        for (int ci = 0; ci < 32; ci++)
            v |= (unsigned)(w2[((co * 32 + ci) * 4 + ky) * 4 + kx] > 0.f) << ci;
        g_w2b[i] = v;
    } else if (t < 160 + 1024 + 640) {   // w3 [10,4096]: word[o][p] bit c = w3[o, c*64+p]
        int i = t - 1184;
        int o = i >> 6, p = i & 63;
        unsigned long long v = 0ull;
        #pragma unroll
        for (int c = 0; c < 64; c++)
            v |= (unsigned long long)(w3[o * 4096 + c * 64 + p] > 0.f) << c;
        g_w3b[i] = v;
    }
}

// ---------------- conv1: bitpacked rows, popcount, + exact channel stats -----
__global__ void __launch_bounds__(224) conv1_kernel(const float* __restrict__ x) {
    __shared__ unsigned xv[28], xm[28];       // value bit / nonzero bit per row
    __shared__ unsigned w1s[160];
    __shared__ unsigned dpk[196 * 9];         // packed int8 dots, stride 9 (pad)
    __shared__ int ps[7 * 32], pq[7 * 32];

    int n = blockIdx.x, t = threadIdx.x;
    int warp = t >> 5, lane = t & 31;

    if (t < 160) w1s[t] = g_w1b[t];

    // coalesced ballot-based input packing: 7 warps x 4 rows
    {
        const float* img = x + (size_t)n * 784;
        #pragma unroll
        for (int rr = 0; rr < 4; rr++) {
            int r = warp * 4 + rr;            // 0..27
            float f = (lane < 28) ? img[r * 28 + lane] : 0.f;
            unsigned v = __ballot_sync(0xFFFFFFFFu, f > 0.f);
            unsigned m = __ballot_sync(0xFFFFFFFFu, f != 0.f);
            if (lane == 0) { xv[r] = v & 0x0FFFFFFFu; xm[r] = m & 0x0FFFFFFFu; }
        }
    }
    __syncthreads();

    if (t < 196) {
        int y = t / 14, xo = t % 14;
        int iy0 = 2 * y - 2, ix0 = 2 * xo - 2;
        unsigned sv[5], sm[5];
        int basec = 0;
        #pragma unroll
        for (int r = 0; r < 5; r++) {
            int iy = iy0 + r;
            unsigned v = 0, m = 0;
            if (iy >= 0 && iy < 28) {
                unsigned xvw = xv[iy], xmw = xm[iy];
                if (ix0 >= 0) { v = xvw >> ix0;     m = xmw >> ix0; }
                else          { v = xvw << (-ix0);  m = xmw << (-ix0); }
                m &= 31u;
            }
            sv[r] = v; sm[r] = m;
            basec += __popc(m);
        }
        unsigned pack[8] = {0, 0, 0, 0, 0, 0, 0, 0};
        #pragma unroll
        for (int co = 0; co < 32; co++) {
            int mm = 0;
            #pragma unroll
            for (int r = 0; r < 5; r++)
                mm += __popc((sv[r] ^ w1s[co * 5 + r]) & sm[r]);
            int d = basec - 2 * mm;            // range [-25, 25]
            pack[co >> 2] |= ((unsigned)d & 0xFFu) << ((co & 3) * 8);
        }
        uint4* dst = (uint4*)(g_c1 + ((size_t)n * 196 + t) * 32);
        dst[0] = make_uint4(pack[0], pack[1], pack[2], pack[3]);
        dst[1] = make_uint4(pack[4], pack[5], pack[6], pack[7]);
        #pragma unroll
        for (int k = 0; k < 8; k++) dpk[t * 9 + k] = pack[k];
    }
    __syncthreads();

    // per-channel block reduction from packed int8 (c = lane, grp = warp)
    {
        int c = lane, grp = warp;
        int s = 0, q = 0;
        #pragma unroll 4
        for (int p = grp; p < 196; p += 7) {
            unsigned w = dpk[p * 9 + (c >> 2)];
            int v = (int)(signed char)(w >> ((c & 3) * 8));
            s += v; q += v * v;
        }
        ps[grp * 32 + c] = s;
        pq[grp * 32 + c] = q;
    }
    __syncthreads();
    if (t < 32) {
        int s = 0, q = 0;
        #pragma unroll
        for (int g = 0; g < 7; g++) { s += ps[g * 32 + t]; q += pq[g * 32 + t]; }
        atomicAdd(&g_stats[t],      (unsigned long long)(long long)s);
        atomicAdd(&g_stats[32 + t], (unsigned long long)(long long)q);
    }
}

// ---------------- conv2: folded bn1, binarize on the fly, XNOR-popcount ------
__global__ void __launch_bounds__(256) conv2_kernel(const float* __restrict__ g1,
                                                    const float* __restrict__ b1) {
    __shared__ unsigned h1s[196];
    __shared__ unsigned w2s[1024];
    __shared__ float m1s[32], s1s[32], b1s[32];
    __shared__ unsigned shm[64 * 36];         // packed int16 dots, stride 36 (pad)
    __shared__ int ps[4 * 64], pq[4 * 64];

    int n = blockIdx.x, t = threadIdx.x;

    for (int i = t; i < 1024; i += 256) w2s[i] = g_w2b[i];
    if (t < 32) {
        // fold bn1 param computation into every block (exact integer stats)
        long long s = (long long)g_stats[t], q = (long long)g_stats[32 + t];
        double cnt = 8192.0 * 196.0;
        double m   = (double)s / cnt;
        double var = (double)q / cnt - m * m;
        m1s[t] = (float)m;
        s1s[t] = (float)((double)g1[t] / sqrt(var + 1e-5));
        b1s[t] = b1[t];
    }
    __syncthreads();

    if (t < 196) {
        const uint4* src = (const uint4*)(g_c1 + ((size_t)n * 196 + t) * 32);
        uint4 a = src[0], bb = src[1];
        unsigned words[8] = {a.x, a.y, a.z, a.w, bb.x, bb.y, bb.z, bb.w};
        unsigned w = 0;
        #pragma unroll
        for (int k = 0; k < 8; k++) {
            unsigned wd = words[k];
            #pragma unroll
            for (int j = 0; j < 4; j++) {
                int c = k * 4 + j;
                int v = (int)(signed char)(wd >> (j * 8));
                float bv = ((float)v - m1s[c]) * s1s[c] + b1s[c];
                w |= (unsigned)(bv > 0.f) << c;
            }
        }
        h1s[t] = w;
    }
    __syncthreads();

    int pos = t & 63, cog = t >> 6;
    int y = pos >> 3, xo = pos & 7;
    unsigned inw[16];
    unsigned vm = 0;
    #pragma unroll
    for (int ky = 0; ky < 4; ky++)
        #pragma unroll
        for (int kx = 0; kx < 4; kx++) {
            int iy = 2 * y - 2 + ky, ix = 2 * xo - 2 + kx;
            int tap = ky * 4 + kx;
            bool valid = (iy >= 0) & (iy < 14) & (ix >= 0) & (ix < 14);
            inw[tap] = valid ? h1s[iy * 14 + ix] : 0u;
            vm |= (unsigned)valid << tap;
        }
    int nval = __popc(vm);
    int cobase = cog * 16;
    int d[16];
    #pragma unroll
    for (int j = 0; j < 16; j++) {
        int co = cobase + j;
        int mm = 0;
        #pragma unroll
        for (int tap = 0; tap < 16; tap++) {
            unsigned wv = w2s[co * 16 + tap];
            if (vm & (1u << tap)) mm += __popc(inw[tap] ^ wv);
        }
        d[j] = 32 * nval - 2 * mm;             // range [-512, 512]
    }
    // pack to int16 pairs
    unsigned u[8];
    #pragma unroll
    for (int k = 0; k < 8; k++)
        u[k] = ((unsigned)d[2 * k] & 0xFFFFu) | ((unsigned)d[2 * k + 1] << 16);
    // global store: [n][pos][co] int16, 32B per thread, sector-aligned
    uint4* gdst = (uint4*)(g_c2 + (size_t)n * 4096 + pos * 64 + cog * 16);
    gdst[0] = make_uint4(u[0], u[1], u[2], u[3]);
    gdst[1] = make_uint4(u[4], u[5], u[6], u[7]);
    // shared store for stats (stride 36 uints -> conflict-free STS.128)
    uint4* sdst = (uint4*)&shm[pos * 36 + cog * 8];
    sdst[0] = make_uint4(u[0], u[1], u[2], u[3]);
    sdst[1] = make_uint4(u[4], u[5], u[6], u[7]);
    __syncthreads();

    // per-channel stats
    {
        int co = t & 63, grp = t >> 6;
        int cg = co >> 4, k = (co & 15) >> 1;
        int s = 0, q = 0;
        #pragma unroll 4
        for (int p = grp; p < 64; p += 4) {
            unsigned w = shm[p * 36 + cg * 8 + k];
            int v = (co & 1) ? (int)(short)(w >> 16) : (int)(short)(w & 0xFFFFu);
            s += v; q += v * v;
        }
        ps[grp * 64 + co] = s;
        pq[grp * 64 + co] = q;
    }
    __syncthreads();
    if (t < 64) {
        int s = 0, q = 0;
        #pragma unroll
        for (int g = 0; g < 4; g++) { s += ps[g * 64 + t]; q += pq[g * 64 + t]; }
        atomicAdd(&g_stats[64 + t],  (unsigned long long)(long long)s);
        atomicAdd(&g_stats[128 + t], (unsigned long long)(long long)q);
    }
}

// ---------------- fc: folded bn2, binarize, 64-bit XNOR-popcount, + stats ----
__global__ void __launch_bounds__(256) fc_kernel(const float* __restrict__ g2,
                                                 const float* __restrict__ b2) {
    __shared__ unsigned long long w3s[640];
    __shared__ float m2s[64], s2s[64], b2s[64];
    __shared__ int warp_part[8][10];

    int t = threadIdx.x;
    for (int i = t; i < 640; i += 256) w3s[i] = g_w3b[i];
    if (t < 64) {
        long long s = (long long)g_stats[64 + t], q = (long long)g_stats[128 + t];
        double cnt = 8192.0 * 64.0;
        double m   = (double)s / cnt;
        double var = (double)q / cnt - m * m;
        m2s[t] = (float)m;
        s2s[t] = (float)((double)g2[t] / sqrt(var + 1e-5));
        b2s[t] = b2[t];
    }
    __syncthreads();

    int sub = t >> 6, p = t & 63;
    int n = blockIdx.x * 4 + sub;

    const uint4* src4 = (const uint4*)(g_c2 + (size_t)n * 4096 + p * 64);
    unsigned long long hw = 0ull;
    #pragma unroll
    for (int k = 0; k < 8; k++) {
        uint4 v4 = src4[k];
        unsigned arr[4] = {v4.x, v4.y, v4.z, v4.w};
        #pragma unroll
        for (int j = 0; j < 4; j++) {
            unsigned wd = arr[j];
            int c0 = k * 8 + j * 2;
            int vlo = (int)(short)(wd & 0xFFFFu);
            int vhi = (int)(short)(wd >> 16);
            float blo = ((float)vlo - m2s[c0])     * s2s[c0]     + b2s[c0];
            float bhi = ((float)vhi - m2s[c0 + 1]) * s2s[c0 + 1] + b2s[c0 + 1];
            hw |= (unsigned long long)(blo > 0.f) << c0;
            hw |= (unsigned long long)(bhi > 0.f) << (c0 + 1);
        }
    }

    int contrib[10];
    #pragma unroll
    for (int o = 0; o < 10; o++)
        contrib[o] = 64 - 2 * __popcll(hw ^ w3s[o * 64 + p]);

    #pragma unroll
    for (int o = 0; o < 10; o++) {
        int v = __reduce_add_sync(0xFFFFFFFFu, contrib[o]);
        if ((t & 31) == 0) warp_part[t >> 5][o] = v;
    }
    __syncthreads();
    if (p < 10) {
        int v = warp_part[sub * 2][p] + warp_part[sub * 2 + 1][p];
        g_fc[(size_t)n * 10 + p] = (short)v;
        atomicAdd(&g_stats[192 + p], (unsigned long long)(long long)v);
        atomicAdd(&g_stats[202 + p], (unsigned long long)(long long)(v * v));
    }
}

// ---------------- final BN1d epilogue ----------------------------------------
__global__ void __launch_bounds__(256) out_kernel(const float* __restrict__ g3,
                                                  const float* __restrict__ b3,
                                                  float* __restrict__ out) {
    __shared__ float sc[10], sh[10];
    int t = threadIdx.x;
    if (t < 10) {
        long long s = (long long)g_stats[192 + t], q = (long long)g_stats[202 + t];
        double m   = (double)s / 8192.0;
        double var = (double)q / 8192.0 - m * m;
        double scale = (double)g3[t] / sqrt(var + 1e-5);
        sc[t] = (float)scale;
        sh[t] = (float)((double)b3[t] - m * scale);
    }
    __syncthreads();
    int i = blockIdx.x * 256 + t;
    if (i < BATCH * 10) {
        int o = i % 10;
        out[i] = fmaf((float)g_fc[i], sc[o], sh[o]);
    }
}

// ---------------- launch ------------------------------------------------------
extern "C" void kernel_launch(void* const* d_in, const int* in_sizes, int n_in,
                              void* d_out, int out_size) {
    const float* x  = (const float*)d_in[0];
    const float* w1 = (const float*)d_in[1];
    const float* g1 = (const float*)d_in[2];
    const float* b1 = (const float*)d_in[3];
    const float* w2 = (const float*)d_in[4];
    const float* g2 = (const float*)d_in[5];
    const float* b2 = (const float*)d_in[6];
    const float* w3 = (const float*)d_in[7];
    const float* g3 = (const float*)d_in[8];
    const float* b3 = (const float*)d_in[9];
    float* out = (float*)d_out;

    init_kernel<<<8, 256>>>(w1, w2, w3);
    conv1_kernel<<<BATCH, 224>>>(x);
    conv2_kernel<<<BATCH, 256>>>(g1, b1);
    fc_kernel<<<BATCH / 4, 256>>>(g2, b2);
    out_kernel<<<(BATCH * 10 + 255) / 256, 256>>>(g3, b3, out);
}